// round 15
// baseline (speedup 1.0000x reference)
#include <cuda_runtime.h>

// YoloLoss: input/target (256, 25, 64, 64) f32 -> scalar f32.
// Row i = (b, y, x). Element (i, c) at base(b) + c*4096 + (i & 4095).
//
// Heterogeneous block specialization, 24 blocks per batch:
//   j in [0,4):  BOX block   — rows j*1024..+1023, channels 0..4, IOU math.
//   j in [4,24): CLASS block — channel c = j+1, full 4096-row plane-pair,
//                pure streaming m*(p-t)^2; mask recomputed from t4 (t4 planes
//                are 4MB total and re-read by adjacent blocks -> L2 resident).
// Tail: per-block fp32 partial -> i64 fixed point (x2^30, exact via double)
// -> atomicAdd(u64) => bit-deterministic; last block writes out + resets.

#define THREADS 256
#define NBATCH  256
#define BPB     24                   // blocks per batch: 4 box + 20 class
#define BLOCKS  (NBATCH * BPB)       // 6144

#define COORD_W 5.0f
#define NOOBJ_W 0.5f
#define INV_BLOCKS (1.0f / 64.0f)
#define FP_SCALE 1073741824.0        // 2^30

__device__ unsigned long long g_sum;        // zero-init; reset by finisher
__device__ unsigned int       g_done_count; // zero-init; reset by finisher

__global__ void __launch_bounds__(THREADS, 4) yolo_loss_fused(
    const float* __restrict__ inp, const float* __restrict__ tgt,
    float* __restrict__ out)
{
    const int bid   = blockIdx.x;
    const int batch = bid / BPB;
    const int j     = bid - batch * BPB;
    const float* __restrict__ pB = inp + (size_t)batch * (25 * 4096);
    const float* __restrict__ tB = tgt + (size_t)batch * (25 * 4096);

    float lsum = 0.0f;

    if (j < 4) {
        // ---------------- BOX block: channels 0..4, 1024 rows ----------------
        const int off = j * 1024 + threadIdx.x * 4;
        const float* __restrict__ pb = pB + off;
        const float* __restrict__ tb = tB + off;

        float P[5][4], T[5][4];
#pragma unroll
        for (int c = 0; c < 5; c++) {
            float4 pv = *reinterpret_cast<const float4*>(pb + c * 4096);
            float4 tv = *reinterpret_cast<const float4*>(tb + c * 4096);
            P[c][0] = pv.x; P[c][1] = pv.y; P[c][2] = pv.z; P[c][3] = pv.w;
            T[c][0] = tv.x; T[c][1] = tv.y; T[c][2] = tv.z; T[c][3] = tv.w;
        }

#pragma unroll
        for (int l = 0; l < 4; l++) {
            const float p0 = P[0][l], p1 = P[1][l], p2 = P[2][l], p3 = P[3][l], p4 = P[4][l];
            const float t0 = T[0][l], t1 = T[1][l], t2 = T[2][l], t3 = T[3][l], t4 = T[4][l];

            const float mm = (t4 > 0.0f) ? 1.0f : 0.0f;

            const float c1x = p0 * INV_BLOCKS, c1y = p1 * INV_BLOCKS;
            const float c2x = t0 * INV_BLOCKS, c2y = t1 * INV_BLOCKS;
            const float x1a = c1x - 0.5f * p2, x2a = c1x + 0.5f * p2;
            const float y1a = c1y - 0.5f * p3, y2a = c1y + 0.5f * p3;
            const float x1b = c2x - 0.5f * t2, x2b = c2x + 0.5f * t2;
            const float y1b = c2y - 0.5f * t3, y2b = c2y + 0.5f * t3;
            const float dx = fminf(x2a, x2b) - fmaxf(x1a, x1b);
            const float dy = fminf(y2a, y2b) - fmaxf(y1a, y1b);
            const float inter = dx * dy;
            const float uni   = p2 * p3 + t2 * t3 - inter;
            const bool  pos   = (dx > 0.0f) && (dy > 0.0f);
            const float iou   = pos ? __fdividef(inter, uni) : 0.0f;

            const float sp2 = sqrtf(p2), sp3 = sqrtf(p3);
            const float st2 = sqrtf(t2), st3 = sqrtf(t3);

            const float dxy = (p0 - t0) * (p0 - t0) + (p1 - t1) * (p1 - t1);
            const float dwh = (sp2 - st2) * (sp2 - st2) + (sp3 - st3) * (sp3 - st3);
            const float dcf = (p4 - iou) * (p4 - iou);
            const float dnb = p4 * p4;

            lsum += mm * (COORD_W * (dxy + dwh) + dcf)
                  + NOOBJ_W * (1.0f - mm) * dnb;
        }
    } else {
        // -------------- CLASS block: channel c = j+1, full plane --------------
        const int c   = j + 1;                  // j=4 -> c=5 ... j=23 -> c=24
        const int off = threadIdx.x * 4;
        const float* __restrict__ t4p = tB + 4 * 4096 + off;  // L2-resident
        const float* __restrict__ pc  = pB + c * 4096 + off;
        const float* __restrict__ tc  = tB + c * 4096 + off;

        // Front-batch t4 (masks) + p planes: 8 independent LDG.128.
        float4 t4v[4], pv[4];
#pragma unroll
        for (int k = 0; k < 4; k++) t4v[k] = *reinterpret_cast<const float4*>(t4p + k * 1024);
#pragma unroll
        for (int k = 0; k < 4; k++) pv[k]  = *reinterpret_cast<const float4*>(pc + k * 1024);

#pragma unroll
        for (int k = 0; k < 4; k++) {
            float4 tv = *reinterpret_cast<const float4*>(tc + k * 1024);
            const float m0 = (t4v[k].x > 0.0f) ? 1.0f : 0.0f;
            const float m1 = (t4v[k].y > 0.0f) ? 1.0f : 0.0f;
            const float m2 = (t4v[k].z > 0.0f) ? 1.0f : 0.0f;
            const float m3 = (t4v[k].w > 0.0f) ? 1.0f : 0.0f;
            const float d0 = pv[k].x - tv.x, d1 = pv[k].y - tv.y;
            const float d2 = pv[k].z - tv.z, d3 = pv[k].w - tv.w;
            lsum += m0 * d0 * d0 + m1 * d1 * d1 + m2 * d2 * d2 + m3 * d3 * d3;
        }
    }

    // ---- warp + block reduce, fixed-point atomic tail ----
#pragma unroll
    for (int o = 16; o > 0; o >>= 1)
        lsum += __shfl_xor_sync(0xFFFFFFFFu, lsum, o);

    __shared__ float ws[THREADS / 32];
    const int lane = threadIdx.x & 31;
    const int warp = threadIdx.x >> 5;
    if (lane == 0) ws[warp] = lsum;
    __syncthreads();

    if (threadIdx.x == 0) {
        float v = 0.0f;
#pragma unroll
        for (int w = 0; w < THREADS / 32; w++) v += ws[w];

        long long q = __double2ll_rn((double)v * FP_SCALE);
        atomicAdd(&g_sum, (unsigned long long)q);   // order-independent
        __threadfence();
        unsigned int prev = atomicAdd(&g_done_count, 1u);
        if (prev == BLOCKS - 1) {
            unsigned long long total = atomicAdd(&g_sum, 0ULL);
            out[0] = (float)((double)(long long)total * (1.0 / FP_SCALE));
            g_done_count = 0;   // reset for next graph replay
            g_sum = 0ULL;
            __threadfence();
        }
    }
}

extern "C" void kernel_launch(void* const* d_in, const int* in_sizes, int n_in,
                              void* d_out, int out_size)
{
    const float* inp = (const float*)d_in[0];
    const float* tgt = (const float*)d_in[1];
    float* out = (float*)d_out;

    yolo_loss_fused<<<BLOCKS, THREADS>>>(inp, tgt, out);
}